// round 1
// baseline (speedup 1.0000x reference)
#include <cuda_runtime.h>
#include <math.h>

// Sinkhorn distance, B=4, P=2048, D=64, eps=0.1, max_iter=100, thresh=0.1
// Output layout: [cost(4) | pi(4*2048*2048) | C(4*2048*2048)]

#define BB 4
#define PP 2048
#define DD 64
#define NROWS (BB*PP)                 // 8192
#define NEL ((size_t)BB*PP*PP)        // 16777216
#define S_CONST 14.426950408889634f   // (1/eps) * log2(e), eps = 0.1
#define EPSLN2  0.069314718055994531f // eps * ln2

__device__ float g_u[NROWS];
__device__ float g_v[NROWS];
__device__ float g_err[NROWS];
__device__ int   g_done[104];
__device__ float g_part[8192];

// exp2 via degree-6 Taylor poly on the FMA pipe (avoids MUFU throughput wall).
// Valid for any x; clamped to [-126, 126]. Rel err ~1.5e-5.
__device__ __forceinline__ float exp2p(float x) {
    x = fmaxf(fminf(x, 126.0f), -126.0f);
    float fl = floorf(x);
    float r  = x - fl;                 // r in [0,1)
    float p  = 1.5403530393381606e-4f;
    p = fmaf(p, r, 1.3333558146428443e-3f);
    p = fmaf(p, r, 9.6181291076284771e-3f);
    p = fmaf(p, r, 5.5504108664821580e-2f);
    p = fmaf(p, r, 2.4022650695910071e-1f);
    p = fmaf(p, r, 6.9314718055994531e-1f);
    p = fmaf(p, r, 1.0f);
    // p in [1,2): add integer exponent directly into the float exponent field
    return __int_as_float(__float_as_int(p) + (((int)fl) << 23));
}

// merge two (max, sum) log2-domain LSE accumulators
__device__ __forceinline__ void lse_merge(float& m, float& s, float m2, float s2) {
    float M = fmaxf(m, m2);
    s = s * exp2p(m - M) + s2 * exp2p(m2 - M);
    m = M;
}

__global__ void kInit() {
    int t = blockIdx.x * 256 + threadIdx.x;
    if (t < NROWS) { g_u[t] = 0.0f; g_v[t] = 0.0f; }
    if (t == 0) g_done[0] = 0;
}

// C[b,i,j] = sum_d (x[b,i,d] - y[b,j,d])^2   (faithful to reference: abs-diff squared)
__global__ void kC(const float* __restrict__ x, const float* __restrict__ y,
                   float* __restrict__ Cout) {
    __shared__ float xs[32][65];
    __shared__ float ys[32][65];
    int b  = blockIdx.z;
    int i0 = blockIdx.y * 32;
    int j0 = blockIdx.x * 32;
    int tid = threadIdx.y * 32 + threadIdx.x;
    int r = tid >> 6;        // 0..15
    int d = tid & 63;
    xs[r     ][d] = x[((size_t)(b*PP + i0 + r     ))*DD + d];
    xs[r + 16][d] = x[((size_t)(b*PP + i0 + r + 16))*DD + d];
    ys[r     ][d] = y[((size_t)(b*PP + j0 + r     ))*DD + d];
    ys[r + 16][d] = y[((size_t)(b*PP + j0 + r + 16))*DD + d];
    __syncthreads();
    float acc = 0.0f;
    #pragma unroll
    for (int dd = 0; dd < DD; dd++) {
        float df = xs[threadIdx.y][dd] - ys[threadIdx.x][dd];
        acc = fmaf(df, df, acc);
    }
    Cout[((size_t)(b*PP + i0 + threadIdx.y))*PP + j0 + threadIdx.x] = acc;
}

// u update: per-row LSE_j((v_j - C_ij)/eps), 8 rows/block, 1 warp/row
__global__ void kU(const float* __restrict__ C, int iter, float eps_log_mu) {
    if (g_done[iter]) return;
    __shared__ float vs[PP];
    int b = blockIdx.x >> 8;                 // 256 blocks per batch
    for (int t = threadIdx.x; t < PP; t += 256)
        vs[t] = g_v[b*PP + t] * S_CONST;
    __syncthreads();
    int w = threadIdx.x >> 5, lane = threadIdx.x & 31;
    int row = blockIdx.x * 8 + w;            // global row 0..8191
    const float* Crow = C + (size_t)row * PP;

    float m0 = -INFINITY, s0 = 0.0f, m1 = -INFINITY, s1 = 0.0f;
    #pragma unroll 8
    for (int k = 0; k < PP/32; k += 2) {
        int j0 = lane + k*32;
        float c0 = Crow[j0];
        float c1 = Crow[j0 + 32];
        float a0 = fmaf(c0, -S_CONST, vs[j0]);
        float a1 = fmaf(c1, -S_CONST, vs[j0 + 32]);
        if (a0 > m0) { s0 = fmaf(s0, exp2p(m0 - a0), 1.0f); m0 = a0; }
        else         { s0 += exp2p(a0 - m0); }
        if (a1 > m1) { s1 = fmaf(s1, exp2p(m1 - a1), 1.0f); m1 = a1; }
        else         { s1 += exp2p(a1 - m1); }
    }
    lse_merge(m0, s0, m1, s1);
    #pragma unroll
    for (int off = 16; off > 0; off >>= 1) {
        float mo = __shfl_down_sync(0xffffffffu, m0, off);
        float so = __shfl_down_sync(0xffffffffu, s0, off);
        lse_merge(m0, s0, mo, so);
    }
    if (lane == 0) {
        float lse2 = m0 + log2f(s0);
        float un = fmaf(-EPSLN2, lse2, eps_log_mu);
        float old = g_u[row];
        g_u[row] = un;
        g_err[row] = fabsf(un - old);
    }
}

// v update: per-col LSE_i((u_i - C_ij)/eps). Block = 32 cols x full 2048 rows,
// 128 threads (4 row-groups of 512 rows per thread). Block 0 also computes the
// deterministic err reduction and writes g_done[iter+1].
__global__ void kV(const float* __restrict__ C, int iter, float eps_log_nu,
                   float thresh_tot) {
    __shared__ float us[PP];
    __shared__ float pm[4][33];
    __shared__ float ps[4][33];
    __shared__ float red[128];
    int done = g_done[iter];
    int b  = blockIdx.x >> 6;
    int j0 = (blockIdx.x & 63) * 32;

    if (!done) {
        for (int t = threadIdx.x; t < PP; t += 128)
            us[t] = g_u[b*PP + t] * S_CONST;
        __syncthreads();
        int cl = threadIdx.x & 31;
        int rg = threadIdx.x >> 5;
        int j  = j0 + cl;
        const float* Cb = C + (size_t)b * PP * PP;
        float m0 = -INFINITY, s0 = 0.0f;
        int r0 = rg * 512;
        #pragma unroll 8
        for (int rr = 0; rr < 512; rr++) {
            int r = r0 + rr;
            float cc = Cb[(size_t)r * PP + j];
            float a = fmaf(cc, -S_CONST, us[r]);
            if (a > m0) { s0 = fmaf(s0, exp2p(m0 - a), 1.0f); m0 = a; }
            else        { s0 += exp2p(a - m0); }
        }
        pm[rg][cl] = m0; ps[rg][cl] = s0;
        __syncthreads();
        if (threadIdx.x < 32) {
            float M = pm[0][cl], SS = ps[0][cl];
            lse_merge(M, SS, pm[1][cl], ps[1][cl]);
            lse_merge(M, SS, pm[2][cl], ps[2][cl]);
            lse_merge(M, SS, pm[3][cl], ps[3][cl]);
            float lse2 = M + log2f(SS);
            g_v[b*PP + j0 + cl] = fmaf(-EPSLN2, lse2, eps_log_nu);
        }
    }

    // done-flag update (reads g_err written by kU this iteration; writes slot
    // iter+1 which no kernel reads until the next iteration -> race-free).
    if (blockIdx.x == 0) {
        __syncthreads();
        float tsum = 0.0f;
        #pragma unroll 8
        for (int k = 0; k < NROWS/128; k++)
            tsum += g_err[threadIdx.x + k*128];
        red[threadIdx.x] = tsum;
        __syncthreads();
        for (int st = 64; st > 0; st >>= 1) {
            if (threadIdx.x < st) red[threadIdx.x] += red[threadIdx.x + st];
            __syncthreads();
        }
        if (threadIdx.x == 0)
            g_done[iter + 1] = done | (red[0] < thresh_tot);
    }
}

// pi = exp((-C + u_i + v_j)/eps); per-block partial of sum(pi*C)
__global__ void kFinal(const float* __restrict__ C, float* __restrict__ pi) {
    __shared__ float red[256];
    int blk = blockIdx.x;                  // 8192 blocks = one row each
    int b = blk >> 11;
    size_t base = (size_t)blk * PP;
    float ui = g_u[blk];
    const float* vrow = g_v + b*PP;
    const float* Crow = C + base;
    float* prow = pi + base;
    float local = 0.0f;
    #pragma unroll
    for (int k = 0; k < 8; k++) {
        int j = k*256 + threadIdx.x;
        float c = Crow[j];
        float f = (ui + vrow[j] - c) * S_CONST;
        float p = exp2p(f);
        prow[j] = p;
        local = fmaf(p, c, local);
    }
    red[threadIdx.x] = local;
    __syncthreads();
    for (int st = 128; st > 0; st >>= 1) {
        if (threadIdx.x < st) red[threadIdx.x] += red[threadIdx.x + st];
        __syncthreads();
    }
    if (threadIdx.x == 0) g_part[blk] = red[0];
}

// deterministic per-batch cost reduction
__global__ void kCost(float* __restrict__ cost) {
    __shared__ float red[256];
    int b = blockIdx.x;
    float t = 0.0f;
    #pragma unroll
    for (int k = 0; k < 8; k++)
        t += g_part[b*2048 + threadIdx.x + k*256];
    red[threadIdx.x] = t;
    __syncthreads();
    for (int st = 128; st > 0; st >>= 1) {
        if (threadIdx.x < st) red[threadIdx.x] += red[threadIdx.x + st];
        __syncthreads();
    }
    if (threadIdx.x == 0) cost[b] = red[0];
}

extern "C" void kernel_launch(void* const* d_in, const int* in_sizes, int n_in,
                              void* d_out, int out_size) {
    const float* x = (const float*)d_in[0];
    const float* y = (const float*)d_in[1];
    float* out  = (float*)d_out;
    float* cost = out;                        // 4
    float* pi   = out + 4;                    // 16777216
    float* C    = out + 4 + (size_t)NEL;      // 16777216

    float log_mu = logf(1.0f/2048.0f + 1e-8f);     // == log_nu (P1==P2)
    float eps_log_mu = 0.1f * log_mu;
    float thresh_tot = 0.1f * (float)BB;           // err*B compared to thresh*B

    kInit<<<(NROWS + 255)/256, 256>>>();
    dim3 gC(PP/32, PP/32, BB);
    kC<<<gC, dim3(32, 32)>>>(x, y, C);
    for (int it = 0; it < 100; it++) {
        kU<<<NROWS/8, 256>>>(C, it, eps_log_mu);
        kV<<<BB*(PP/32), 128>>>(C, it, eps_log_mu, thresh_tot);
    }
    kFinal<<<NROWS, 256>>>(C, pi);
    kCost<<<BB, 256>>>(cost);
}

// round 2
// speedup vs baseline: 3.6533x; 3.6533x over previous
#include <cuda_runtime.h>
#include <math.h>

// Sinkhorn distance, B=4, P=2048, D=64, eps=0.1, max_iter=100, thresh=0.1
// Output layout: [cost(4) | pi(4*2048*2048) | C(4*2048*2048)]

#define BB 4
#define PP 2048
#define DD 64
#define NROWS (BB*PP)                 // 8192
#define NEL ((size_t)BB*PP*PP)        // 16777216
#define S_CONST 14.426950408889634f   // (1/eps) * log2(e), eps = 0.1
#define EPSLN2  0.069314718055994531f // eps * ln2
#define MAGIC   12582912.0f           // 2^23 + 2^22

__device__ float g_u[NROWS];
__device__ float g_v[NROWS];
__device__ float g_err[NROWS];
__device__ float g_xn[NROWS];
__device__ float g_yn[NROWS];
__device__ int   g_done[104];
__device__ float g_part[NROWS];

// Fast exp2 for x <= 0 (post max-subtraction). Magic-number round-to-nearest,
// degree-5 poly for 2^r on [-0.5, 0.5], exponent via integer bit add.
// All on the FMA pipe; ~9 fma-class ops. Rel err ~2.4e-6.
__device__ __forceinline__ float exp2m(float x) {
    x = fmaxf(x, -126.0f);
    float t = __fadd_rn(x, MAGIC);
    float fl = __fsub_rn(t, MAGIC);
    float r = __fsub_rn(x, fl);
    float p =              1.3333558146428443e-3f;
    p = fmaf(p, r, 9.6181291076284771e-3f);
    p = fmaf(p, r, 5.5504108664821580e-2f);
    p = fmaf(p, r, 2.4022650695910071e-1f);
    p = fmaf(p, r, 6.9314718055994531e-1f);
    p = fmaf(p, r, 1.0f);
    return __int_as_float(__float_as_int(p) + (__float_as_int(t) << 23));
}

// General exp2 (both-side clamp) for the final pi computation.
__device__ __forceinline__ float exp2g(float x) {
    x = fminf(fmaxf(x, -126.0f), 126.0f);
    float t = __fadd_rn(x, MAGIC);
    float fl = __fsub_rn(t, MAGIC);
    float r = __fsub_rn(x, fl);
    float p =              1.3333558146428443e-3f;
    p = fmaf(p, r, 9.6181291076284771e-3f);
    p = fmaf(p, r, 5.5504108664821580e-2f);
    p = fmaf(p, r, 2.4022650695910071e-1f);
    p = fmaf(p, r, 6.9314718055994531e-1f);
    p = fmaf(p, r, 1.0f);
    return __int_as_float(__float_as_int(p) + (__float_as_int(t) << 23));
}

__global__ void kInit() {
    int t = blockIdx.x * 256 + threadIdx.x;
    if (t < NROWS) { g_u[t] = 0.0f; g_v[t] = 0.0f; }
    if (t == 0) g_done[0] = 0;
}

// Row norms of x and y: ||row||^2. One warp per row.
__global__ void kNorm(const float* __restrict__ x, const float* __restrict__ y) {
    int lane = threadIdx.x & 31;
    int gw = blockIdx.x * 8 + (threadIdx.x >> 5);  // 0..16383
    const float* src = (gw < NROWS) ? x : y;
    float* dst = (gw < NROWS) ? g_xn : g_yn;
    int row = gw & (NROWS - 1);
    float2 v = ((const float2*)src)[row * 32 + lane];
    float s = fmaf(v.x, v.x, v.y * v.y);
    #pragma unroll
    for (int off = 16; off > 0; off >>= 1)
        s += __shfl_xor_sync(0xffffffffu, s, off);
    if (lane == 0) dst[row] = s;
}

// C[b,i,j] = ||x_i||^2 + ||y_j||^2 - 2 x_i . y_j
// 64x64 tile per block, 256 threads, 4x4 register micro-tile, transposed smem.
__global__ __launch_bounds__(256) void kC(const float* __restrict__ x,
                                          const float* __restrict__ y,
                                          float* __restrict__ Cout) {
    __shared__ float xs[64][68];
    __shared__ float ys[64][68];
    int b  = blockIdx.z;
    int i0 = blockIdx.y * 64;
    int j0 = blockIdx.x * 64;
    for (int idx = threadIdx.x; idx < 64 * 64; idx += 256) {
        int i = idx >> 6, d = idx & 63;
        xs[d][i] = x[((size_t)(b * PP + i0 + i)) * DD + d];
        ys[d][i] = y[((size_t)(b * PP + j0 + i)) * DD + d];
    }
    __syncthreads();
    int tx = threadIdx.x & 15, ty = threadIdx.x >> 4;
    float acc[4][4] = {};
    #pragma unroll 16
    for (int d = 0; d < 64; d++) {
        float4 xv = *(const float4*)&xs[d][ty * 4];
        float4 yv = *(const float4*)&ys[d][tx * 4];
        acc[0][0] = fmaf(xv.x, yv.x, acc[0][0]);
        acc[0][1] = fmaf(xv.x, yv.y, acc[0][1]);
        acc[0][2] = fmaf(xv.x, yv.z, acc[0][2]);
        acc[0][3] = fmaf(xv.x, yv.w, acc[0][3]);
        acc[1][0] = fmaf(xv.y, yv.x, acc[1][0]);
        acc[1][1] = fmaf(xv.y, yv.y, acc[1][1]);
        acc[1][2] = fmaf(xv.y, yv.z, acc[1][2]);
        acc[1][3] = fmaf(xv.y, yv.w, acc[1][3]);
        acc[2][0] = fmaf(xv.z, yv.x, acc[2][0]);
        acc[2][1] = fmaf(xv.z, yv.y, acc[2][1]);
        acc[2][2] = fmaf(xv.z, yv.z, acc[2][2]);
        acc[2][3] = fmaf(xv.z, yv.w, acc[2][3]);
        acc[3][0] = fmaf(xv.w, yv.x, acc[3][0]);
        acc[3][1] = fmaf(xv.w, yv.y, acc[3][1]);
        acc[3][2] = fmaf(xv.w, yv.z, acc[3][2]);
        acc[3][3] = fmaf(xv.w, yv.w, acc[3][3]);
    }
    int gi = b * PP + i0 + ty * 4;
    int gj = b * PP + j0 + tx * 4;
    float xn0 = g_xn[gi + 0], xn1 = g_xn[gi + 1], xn2 = g_xn[gi + 2], xn3 = g_xn[gi + 3];
    float yn0 = g_yn[gj + 0], yn1 = g_yn[gj + 1], yn2 = g_yn[gj + 2], yn3 = g_yn[gj + 3];
    float xn[4] = {xn0, xn1, xn2, xn3};
    float yn[4] = {yn0, yn1, yn2, yn3};
    #pragma unroll
    for (int r = 0; r < 4; r++) {
        float4 o;
        o.x = fmaf(-2.0f, acc[r][0], xn[r] + yn[0]);
        o.y = fmaf(-2.0f, acc[r][1], xn[r] + yn[1]);
        o.z = fmaf(-2.0f, acc[r][2], xn[r] + yn[2]);
        o.w = fmaf(-2.0f, acc[r][3], xn[r] + yn[3]);
        ((float4*)(Cout + ((size_t)(b * PP + i0 + ty * 4 + r)) * PP + j0))[tx] = o;
    }
}

// u update: per-row LSE_j((v_j - C_ij)/eps). 1 warp/row, 8 rows/block.
// Row values kept register-resident between max pass and sum pass.
__global__ __launch_bounds__(256) void kU(const float* __restrict__ C, int iter,
                                          float eps_log_mu) {
    if (g_done[iter]) return;
    __shared__ __align__(16) float vs[PP];
    int b = blockIdx.x >> 8;
    const float4* vb = (const float4*)(g_v + b * PP);
    for (int t = threadIdx.x; t < PP / 4; t += 256) {
        float4 v = vb[t];
        v.x *= S_CONST; v.y *= S_CONST; v.z *= S_CONST; v.w *= S_CONST;
        ((float4*)vs)[t] = v;
    }
    __syncthreads();
    int w = threadIdx.x >> 5, lane = threadIdx.x & 31;
    int row = blockIdx.x * 8 + w;
    const float4* Crow = (const float4*)(C + (size_t)row * PP);
    const float4* vs4 = (const float4*)vs;

    float4 av[16];
    float m0 = -INFINITY, m1 = -INFINITY, m2 = -INFINITY, m3 = -INFINITY;
    #pragma unroll
    for (int k = 0; k < 16; k++) {
        int idx = lane + k * 32;
        float4 c4 = Crow[idx];
        float4 v4 = vs4[idx];
        av[k].x = fmaf(c4.x, -S_CONST, v4.x);
        av[k].y = fmaf(c4.y, -S_CONST, v4.y);
        av[k].z = fmaf(c4.z, -S_CONST, v4.z);
        av[k].w = fmaf(c4.w, -S_CONST, v4.w);
        m0 = fmaxf(m0, av[k].x);
        m1 = fmaxf(m1, av[k].y);
        m2 = fmaxf(m2, av[k].z);
        m3 = fmaxf(m3, av[k].w);
    }
    float m = fmaxf(fmaxf(m0, m1), fmaxf(m2, m3));
    #pragma unroll
    for (int off = 16; off > 0; off >>= 1)
        m = fmaxf(m, __shfl_xor_sync(0xffffffffu, m, off));

    float s0 = 0.0f, s1 = 0.0f, s2 = 0.0f, s3 = 0.0f;
    #pragma unroll
    for (int k = 0; k < 16; k++) {
        s0 += exp2m(av[k].x - m);
        s1 += exp2m(av[k].y - m);
        s2 += exp2m(av[k].z - m);
        s3 += exp2m(av[k].w - m);
    }
    float s = (s0 + s1) + (s2 + s3);
    #pragma unroll
    for (int off = 16; off > 0; off >>= 1)
        s += __shfl_xor_sync(0xffffffffu, s, off);

    if (lane == 0) {
        float lse2 = m + __log2f(s);
        float un = fmaf(-EPSLN2, lse2, eps_log_mu);
        float old = g_u[row];
        g_u[row] = un;
        g_err[row] = fabsf(un - old);
    }
}

// v update: per-col LSE_i((u_i - C_ij)/eps). Block = 32-col stripe x 2048 rows,
// 1024 threads (32 warps x 64 rows each). Two passes over C (max, then sum).
// Block 0 also computes the deterministic err reduction -> g_done[iter+1].
__global__ __launch_bounds__(1024) void kV(const float* __restrict__ C, int iter,
                                           float eps_log_nu, float thresh_tot) {
    __shared__ __align__(16) float us[PP];
    __shared__ float sm[32 * 32];
    __shared__ float mcol[32];
    __shared__ float red[1024];
    int done = g_done[iter];
    int b  = blockIdx.x >> 6;
    int j0 = (blockIdx.x & 63) * 32;
    int w = threadIdx.x >> 5, lane = threadIdx.x & 31;

    if (!done) {
        const float4* ub = (const float4*)(g_u + b * PP);
        for (int t = threadIdx.x; t < PP / 4; t += 1024) {
            float4 u4 = ub[t];
            u4.x *= S_CONST; u4.y *= S_CONST; u4.z *= S_CONST; u4.w *= S_CONST;
            ((float4*)us)[t] = u4;
        }
        __syncthreads();
        int j = j0 + lane;
        const float* Cp = C + (size_t)b * PP * PP + (size_t)(w * 64) * PP + j;
        const float* ur = us + w * 64;

        // pass A: max
        float m0 = -INFINITY, m1 = -INFINITY, m2 = -INFINITY, m3 = -INFINITY;
        {
            const float* p = Cp;
            #pragma unroll 4
            for (int rr = 0; rr < 64; rr += 4) {
                float c0 = p[0];
                float c1 = p[PP];
                float c2 = p[2 * PP];
                float c3 = p[3 * PP];
                m0 = fmaxf(m0, fmaf(c0, -S_CONST, ur[rr + 0]));
                m1 = fmaxf(m1, fmaf(c1, -S_CONST, ur[rr + 1]));
                m2 = fmaxf(m2, fmaf(c2, -S_CONST, ur[rr + 2]));
                m3 = fmaxf(m3, fmaf(c3, -S_CONST, ur[rr + 3]));
                p += 4 * PP;
            }
        }
        sm[w * 32 + lane] = fmaxf(fmaxf(m0, m1), fmaxf(m2, m3));
        __syncthreads();
        if (threadIdx.x < 32) {
            float mm = -INFINITY;
            #pragma unroll
            for (int k = 0; k < 32; k++) mm = fmaxf(mm, sm[k * 32 + threadIdx.x]);
            mcol[threadIdx.x] = mm;
        }
        __syncthreads();
        float mj = mcol[lane];

        // pass B: sum of exp2(a - mj)
        float s0 = 0.0f, s1 = 0.0f, s2 = 0.0f, s3 = 0.0f;
        {
            const float* p = Cp;
            #pragma unroll 4
            for (int rr = 0; rr < 64; rr += 4) {
                float c0 = p[0];
                float c1 = p[PP];
                float c2 = p[2 * PP];
                float c3 = p[3 * PP];
                s0 += exp2m(fmaf(c0, -S_CONST, ur[rr + 0]) - mj);
                s1 += exp2m(fmaf(c1, -S_CONST, ur[rr + 1]) - mj);
                s2 += exp2m(fmaf(c2, -S_CONST, ur[rr + 2]) - mj);
                s3 += exp2m(fmaf(c3, -S_CONST, ur[rr + 3]) - mj);
                p += 4 * PP;
            }
        }
        __syncthreads();   // sm reuse
        sm[w * 32 + lane] = (s0 + s1) + (s2 + s3);
        __syncthreads();
        if (threadIdx.x < 32) {
            float ss = 0.0f;
            #pragma unroll
            for (int k = 0; k < 32; k++) ss += sm[k * 32 + threadIdx.x];
            float lse2 = mcol[threadIdx.x] + __log2f(ss);
            g_v[b * PP + j0 + threadIdx.x] = fmaf(-EPSLN2, lse2, eps_log_nu);
        }
    }

    // done-flag: deterministic reduction of per-row |du| (writes slot iter+1)
    if (blockIdx.x == 0) {
        __syncthreads();
        float tsum = 0.0f;
        #pragma unroll
        for (int k = 0; k < NROWS / 1024; k++)
            tsum += g_err[threadIdx.x + k * 1024];
        red[threadIdx.x] = tsum;
        __syncthreads();
        for (int st = 512; st > 0; st >>= 1) {
            if (threadIdx.x < st) red[threadIdx.x] += red[threadIdx.x + st];
            __syncthreads();
        }
        if (threadIdx.x == 0)
            g_done[iter + 1] = done | (red[0] < thresh_tot);
    }
}

// pi = exp((-C + u_i + v_j)/eps); per-block (per-row) partial of sum(pi*C)
__global__ __launch_bounds__(256) void kFinal(const float* __restrict__ C,
                                              float* __restrict__ pi) {
    __shared__ __align__(16) float ws[PP];
    __shared__ float red[256];
    int row = blockIdx.x;
    int b = row >> 11;
    float ui = g_u[row];
    const float4* vb = (const float4*)(g_v + b * PP);
    for (int t = threadIdx.x; t < PP / 4; t += 256) {
        float4 v4 = vb[t];
        v4.x = (ui + v4.x) * S_CONST;
        v4.y = (ui + v4.y) * S_CONST;
        v4.z = (ui + v4.z) * S_CONST;
        v4.w = (ui + v4.w) * S_CONST;
        ((float4*)ws)[t] = v4;
    }
    __syncthreads();
    const float4* Crow = (const float4*)(C + (size_t)row * PP);
    float4* prow = (float4*)(pi + (size_t)row * PP);
    const float4* ws4 = (const float4*)ws;
    float local = 0.0f;
    #pragma unroll
    for (int k = 0; k < 2; k++) {
        int idx = threadIdx.x + k * 256;
        float4 c4 = Crow[idx];
        float4 w4 = ws4[idx];
        float4 p4;
        p4.x = exp2g(fmaf(c4.x, -S_CONST, w4.x));
        p4.y = exp2g(fmaf(c4.y, -S_CONST, w4.y));
        p4.z = exp2g(fmaf(c4.z, -S_CONST, w4.z));
        p4.w = exp2g(fmaf(c4.w, -S_CONST, w4.w));
        prow[idx] = p4;
        local = fmaf(p4.x, c4.x, local);
        local = fmaf(p4.y, c4.y, local);
        local = fmaf(p4.z, c4.z, local);
        local = fmaf(p4.w, c4.w, local);
    }
    red[threadIdx.x] = local;
    __syncthreads();
    for (int st = 128; st > 0; st >>= 1) {
        if (threadIdx.x < st) red[threadIdx.x] += red[threadIdx.x + st];
        __syncthreads();
    }
    if (threadIdx.x == 0) g_part[row] = red[0];
}

// deterministic per-batch cost reduction
__global__ void kCost(float* __restrict__ cost) {
    __shared__ float red[256];
    int b = blockIdx.x;
    float t = 0.0f;
    #pragma unroll
    for (int k = 0; k < 8; k++)
        t += g_part[b * 2048 + threadIdx.x + k * 256];
    red[threadIdx.x] = t;
    __syncthreads();
    for (int st = 128; st > 0; st >>= 1) {
        if (threadIdx.x < st) red[threadIdx.x] += red[threadIdx.x + st];
        __syncthreads();
    }
    if (threadIdx.x == 0) cost[b] = red[0];
}

extern "C" void kernel_launch(void* const* d_in, const int* in_sizes, int n_in,
                              void* d_out, int out_size) {
    const float* x = (const float*)d_in[0];
    const float* y = (const float*)d_in[1];
    float* out  = (float*)d_out;
    float* cost = out;                        // 4
    float* pi   = out + 4;                    // 16777216
    float* C    = out + 4 + (size_t)NEL;      // 16777216

    float log_mu = logf(1.0f / 2048.0f + 1e-8f);   // == log_nu (P1==P2)
    float eps_log_mu = 0.1f * log_mu;
    float thresh_tot = 0.1f * (float)BB;           // sum-over-all-rows vs thresh*B

    kInit<<<(NROWS + 255) / 256, 256>>>();
    kNorm<<<2 * NROWS / 8, 256>>>(x, y);
    dim3 gC(PP / 64, PP / 64, BB);
    kC<<<gC, 256>>>(x, y, C);
    for (int it = 0; it < 100; it++) {
        kU<<<NROWS / 8, 256>>>(C, it, eps_log_mu);
        kV<<<BB * (PP / 32), 1024>>>(C, it, eps_log_mu, thresh_tot);
    }
    kFinal<<<NROWS, 256>>>(C, pi);
    kCost<<<BB, 256>>>(cost);
}

// round 3
// speedup vs baseline: 6.0603x; 1.6589x over previous
#include <cuda_runtime.h>
#include <math.h>

// Sinkhorn distance, B=4, P=2048, D=64, eps=0.1, max_iter=100, thresh=0.1
// Output layout: [cost(4) | pi(4*2048*2048) | C(4*2048*2048)]

#define BB 4
#define PP 2048
#define DD 64
#define NROWS (BB*PP)                 // 8192
#define NEL ((size_t)BB*PP*PP)        // 16777216
#define S_CONST 14.426950408889634f   // (1/eps) * log2(e), eps = 0.1
#define EPSLN2  0.069314718055994531f // eps * ln2

__device__ float g_u[NROWS];
__device__ float g_v[NROWS];
__device__ float g_err[NROWS];
__device__ float g_xn[NROWS];
__device__ float g_yn[NROWS];
__device__ int   g_done[104];
__device__ float g_part[NROWS];

// Hardware exp2 on the MUFU pipe (warp-wide, 32 lanes / 8 cyc / SMSP).
// Handles full range incl. underflow->0. ~2 ulp.
__device__ __forceinline__ float ex2(float x) {
    float r;
    asm("ex2.approx.ftz.f32 %0, %1;" : "=f"(r) : "f"(x));
    return r;
}

__global__ void kInit() {
    int t = blockIdx.x * 256 + threadIdx.x;
    if (t < NROWS) { g_u[t] = 0.0f; g_v[t] = 0.0f; }
    if (t == 0) g_done[0] = 0;
}

// Row norms of x and y: ||row||^2. One warp per row.
__global__ void kNorm(const float* __restrict__ x, const float* __restrict__ y) {
    int lane = threadIdx.x & 31;
    int gw = blockIdx.x * 8 + (threadIdx.x >> 5);  // 0..16383
    const float* src = (gw < NROWS) ? x : y;
    float* dst = (gw < NROWS) ? g_xn : g_yn;
    int row = gw & (NROWS - 1);
    float2 v = ((const float2*)src)[row * 32 + lane];
    float s = fmaf(v.x, v.x, v.y * v.y);
    #pragma unroll
    for (int off = 16; off > 0; off >>= 1)
        s += __shfl_xor_sync(0xffffffffu, s, off);
    if (lane == 0) dst[row] = s;
}

// C[b,i,j] = ||x_i||^2 + ||y_j||^2 - 2 x_i . y_j
// 64x64 tile per block, 256 threads, 4x4 register micro-tile, transposed smem.
__global__ __launch_bounds__(256) void kC(const float* __restrict__ x,
                                          const float* __restrict__ y,
                                          float* __restrict__ Cout) {
    __shared__ float xs[64][68];
    __shared__ float ys[64][68];
    int b  = blockIdx.z;
    int i0 = blockIdx.y * 64;
    int j0 = blockIdx.x * 64;
    for (int idx = threadIdx.x; idx < 64 * 64; idx += 256) {
        int i = idx >> 6, d = idx & 63;
        xs[d][i] = x[((size_t)(b * PP + i0 + i)) * DD + d];
        ys[d][i] = y[((size_t)(b * PP + j0 + i)) * DD + d];
    }
    __syncthreads();
    int tx = threadIdx.x & 15, ty = threadIdx.x >> 4;
    float acc[4][4] = {};
    #pragma unroll 16
    for (int d = 0; d < 64; d++) {
        float4 xv = *(const float4*)&xs[d][ty * 4];
        float4 yv = *(const float4*)&ys[d][tx * 4];
        acc[0][0] = fmaf(xv.x, yv.x, acc[0][0]);
        acc[0][1] = fmaf(xv.x, yv.y, acc[0][1]);
        acc[0][2] = fmaf(xv.x, yv.z, acc[0][2]);
        acc[0][3] = fmaf(xv.x, yv.w, acc[0][3]);
        acc[1][0] = fmaf(xv.y, yv.x, acc[1][0]);
        acc[1][1] = fmaf(xv.y, yv.y, acc[1][1]);
        acc[1][2] = fmaf(xv.y, yv.z, acc[1][2]);
        acc[1][3] = fmaf(xv.y, yv.w, acc[1][3]);
        acc[2][0] = fmaf(xv.z, yv.x, acc[2][0]);
        acc[2][1] = fmaf(xv.z, yv.y, acc[2][1]);
        acc[2][2] = fmaf(xv.z, yv.z, acc[2][2]);
        acc[2][3] = fmaf(xv.z, yv.w, acc[2][3]);
        acc[3][0] = fmaf(xv.w, yv.x, acc[3][0]);
        acc[3][1] = fmaf(xv.w, yv.y, acc[3][1]);
        acc[3][2] = fmaf(xv.w, yv.z, acc[3][2]);
        acc[3][3] = fmaf(xv.w, yv.w, acc[3][3]);
    }
    int gi = b * PP + i0 + ty * 4;
    int gj = b * PP + j0 + tx * 4;
    float xn[4] = {g_xn[gi], g_xn[gi + 1], g_xn[gi + 2], g_xn[gi + 3]};
    float yn[4] = {g_yn[gj], g_yn[gj + 1], g_yn[gj + 2], g_yn[gj + 3]};
    #pragma unroll
    for (int r = 0; r < 4; r++) {
        float4 o;
        o.x = fmaf(-2.0f, acc[r][0], xn[r] + yn[0]);
        o.y = fmaf(-2.0f, acc[r][1], xn[r] + yn[1]);
        o.z = fmaf(-2.0f, acc[r][2], xn[r] + yn[2]);
        o.w = fmaf(-2.0f, acc[r][3], xn[r] + yn[3]);
        ((float4*)(Cout + ((size_t)(b * PP + i0 + ty * 4 + r)) * PP + j0))[tx] = o;
    }
}

// u update: per-row LSE_j((v_j - C_ij)/eps). 4 rows/block, 64 threads/row,
// 32 elems cached per thread (single read of C), EX2 on MUFU pipe.
__global__ __launch_bounds__(256) void kU(const float* __restrict__ C, int iter,
                                          float eps_log_mu) {
    if (g_done[iter]) return;
    __shared__ __align__(16) float vs[PP];
    __shared__ float wmax[8];
    __shared__ float wsum[8];
    int b = blockIdx.x >> 9;                 // 512 blocks per batch (4 rows each)
    const float4* vb = (const float4*)(g_v + b * PP);
    for (int t = threadIdx.x; t < PP / 4; t += 256) {
        float4 v = vb[t];
        v.x *= S_CONST; v.y *= S_CONST; v.z *= S_CONST; v.w *= S_CONST;
        ((float4*)vs)[t] = v;
    }
    __syncthreads();
    int w    = threadIdx.x >> 5;             // warp 0..7
    int lane = threadIdx.x & 31;
    int r    = threadIdx.x >> 6;             // row-in-block 0..3
    int t64  = threadIdx.x & 63;             // thread-in-row
    int row  = blockIdx.x * 4 + r;
    const float4* Crow = (const float4*)(C + (size_t)row * PP);
    const float4* vs4  = (const float4*)vs;

    float4 av[8];
    float m0 = -INFINITY, m1 = -INFINITY, m2 = -INFINITY, m3 = -INFINITY;
    #pragma unroll
    for (int k = 0; k < 8; k++) {
        int idx = t64 + k * 64;
        float4 c4 = Crow[idx];
        float4 v4 = vs4[idx];
        av[k].x = fmaf(c4.x, -S_CONST, v4.x);
        av[k].y = fmaf(c4.y, -S_CONST, v4.y);
        av[k].z = fmaf(c4.z, -S_CONST, v4.z);
        av[k].w = fmaf(c4.w, -S_CONST, v4.w);
        m0 = fmaxf(m0, av[k].x);
        m1 = fmaxf(m1, av[k].y);
        m2 = fmaxf(m2, av[k].z);
        m3 = fmaxf(m3, av[k].w);
    }
    float m = fmaxf(fmaxf(m0, m1), fmaxf(m2, m3));
    #pragma unroll
    for (int off = 16; off > 0; off >>= 1)
        m = fmaxf(m, __shfl_xor_sync(0xffffffffu, m, off));
    if (lane == 0) wmax[w] = m;
    __syncthreads();
    m = fmaxf(wmax[r * 2], wmax[r * 2 + 1]);

    float s0 = 0.0f, s1 = 0.0f, s2 = 0.0f, s3 = 0.0f;
    #pragma unroll
    for (int k = 0; k < 8; k++) {
        s0 += ex2(av[k].x - m);
        s1 += ex2(av[k].y - m);
        s2 += ex2(av[k].z - m);
        s3 += ex2(av[k].w - m);
    }
    float s = (s0 + s1) + (s2 + s3);
    #pragma unroll
    for (int off = 16; off > 0; off >>= 1)
        s += __shfl_xor_sync(0xffffffffu, s, off);
    if (lane == 0) wsum[w] = s;
    __syncthreads();
    if (t64 == 0) {
        float st = wsum[r * 2] + wsum[r * 2 + 1];
        float lse2 = m + __log2f(st);
        float un = fmaf(-EPSLN2, lse2, eps_log_mu);
        float old = g_u[row];
        g_u[row] = un;
        g_err[row] = fabsf(un - old);
    }
}

// v update: per-col LSE_i((u_i - C_ij)/eps). Block = 32-col stripe x 2048 rows,
// 1024 threads (32 warps x 64 rows each). Two passes over C (max, then sum),
// EX2 on MUFU. Block 0 also does the deterministic err reduction.
__global__ __launch_bounds__(1024) void kV(const float* __restrict__ C, int iter,
                                           float eps_log_nu, float thresh_tot) {
    __shared__ __align__(16) float us[PP];
    __shared__ float sm[32 * 32];
    __shared__ float mcol[32];
    __shared__ float red[1024];
    int done = g_done[iter];
    int b  = blockIdx.x >> 6;
    int j0 = (blockIdx.x & 63) * 32;
    int w = threadIdx.x >> 5, lane = threadIdx.x & 31;

    if (!done) {
        const float4* ub = (const float4*)(g_u + b * PP);
        for (int t = threadIdx.x; t < PP / 4; t += 1024) {
            float4 u4 = ub[t];
            u4.x *= S_CONST; u4.y *= S_CONST; u4.z *= S_CONST; u4.w *= S_CONST;
            ((float4*)us)[t] = u4;
        }
        __syncthreads();
        int j = j0 + lane;
        const float* Cp = C + (size_t)b * PP * PP + (size_t)(w * 64) * PP + j;
        const float* ur = us + w * 64;

        // pass A: column max
        float m0 = -INFINITY, m1 = -INFINITY, m2 = -INFINITY, m3 = -INFINITY;
        {
            const float* p = Cp;
            #pragma unroll 4
            for (int rr = 0; rr < 64; rr += 4) {
                float c0 = p[0];
                float c1 = p[PP];
                float c2 = p[2 * PP];
                float c3 = p[3 * PP];
                m0 = fmaxf(m0, fmaf(c0, -S_CONST, ur[rr + 0]));
                m1 = fmaxf(m1, fmaf(c1, -S_CONST, ur[rr + 1]));
                m2 = fmaxf(m2, fmaf(c2, -S_CONST, ur[rr + 2]));
                m3 = fmaxf(m3, fmaf(c3, -S_CONST, ur[rr + 3]));
                p += 4 * PP;
            }
        }
        sm[w * 32 + lane] = fmaxf(fmaxf(m0, m1), fmaxf(m2, m3));
        __syncthreads();
        if (threadIdx.x < 32) {
            float mm = -INFINITY;
            #pragma unroll
            for (int k = 0; k < 32; k++) mm = fmaxf(mm, sm[k * 32 + threadIdx.x]);
            mcol[threadIdx.x] = mm;
        }
        __syncthreads();
        float mj = mcol[lane];

        // pass B: sum of exp2(a - mj)
        float s0 = 0.0f, s1 = 0.0f, s2 = 0.0f, s3 = 0.0f;
        {
            const float* p = Cp;
            #pragma unroll 4
            for (int rr = 0; rr < 64; rr += 4) {
                float c0 = p[0];
                float c1 = p[PP];
                float c2 = p[2 * PP];
                float c3 = p[3 * PP];
                s0 += ex2(fmaf(c0, -S_CONST, ur[rr + 0]) - mj);
                s1 += ex2(fmaf(c1, -S_CONST, ur[rr + 1]) - mj);
                s2 += ex2(fmaf(c2, -S_CONST, ur[rr + 2]) - mj);
                s3 += ex2(fmaf(c3, -S_CONST, ur[rr + 3]) - mj);
                p += 4 * PP;
            }
        }
        __syncthreads();   // sm reuse
        sm[w * 32 + lane] = (s0 + s1) + (s2 + s3);
        __syncthreads();
        if (threadIdx.x < 32) {
            float ss = 0.0f;
            #pragma unroll
            for (int k = 0; k < 32; k++) ss += sm[k * 32 + threadIdx.x];
            float lse2 = mcol[threadIdx.x] + __log2f(ss);
            g_v[b * PP + j0 + threadIdx.x] = fmaf(-EPSLN2, lse2, eps_log_nu);
        }
    }

    // done-flag: deterministic reduction of per-row |du| (writes slot iter+1)
    if (blockIdx.x == 0) {
        if (done) {
            if (threadIdx.x == 0) g_done[iter + 1] = 1;
            return;
        }
        __syncthreads();
        float tsum = 0.0f;
        #pragma unroll
        for (int k = 0; k < NROWS / 1024; k++)
            tsum += g_err[threadIdx.x + k * 1024];
        red[threadIdx.x] = tsum;
        __syncthreads();
        for (int st = 512; st > 0; st >>= 1) {
            if (threadIdx.x < st) red[threadIdx.x] += red[threadIdx.x + st];
            __syncthreads();
        }
        if (threadIdx.x == 0)
            g_done[iter + 1] = (red[0] < thresh_tot) ? 1 : 0;
    }
}

// pi = exp((-C + u_i + v_j)/eps); per-block (per-row) partial of sum(pi*C)
__global__ __launch_bounds__(256) void kFinal(const float* __restrict__ C,
                                              float* __restrict__ pi) {
    __shared__ __align__(16) float ws[PP];
    __shared__ float red[256];
    int row = blockIdx.x;
    int b = row >> 11;
    float ui = g_u[row];
    const float4* vb = (const float4*)(g_v + b * PP);
    for (int t = threadIdx.x; t < PP / 4; t += 256) {
        float4 v4 = vb[t];
        v4.x = (ui + v4.x) * S_CONST;
        v4.y = (ui + v4.y) * S_CONST;
        v4.z = (ui + v4.z) * S_CONST;
        v4.w = (ui + v4.w) * S_CONST;
        ((float4*)ws)[t] = v4;
    }
    __syncthreads();
    const float4* Crow = (const float4*)(C + (size_t)row * PP);
    float4* prow = (float4*)(pi + (size_t)row * PP);
    const float4* ws4 = (const float4*)ws;
    float local = 0.0f;
    #pragma unroll
    for (int k = 0; k < 2; k++) {
        int idx = threadIdx.x + k * 256;
        float4 c4 = Crow[idx];
        float4 w4 = ws4[idx];
        float4 p4;
        p4.x = ex2(fmaf(c4.x, -S_CONST, w4.x));
        p4.y = ex2(fmaf(c4.y, -S_CONST, w4.y));
        p4.z = ex2(fmaf(c4.z, -S_CONST, w4.z));
        p4.w = ex2(fmaf(c4.w, -S_CONST, w4.w));
        prow[idx] = p4;
        local = fmaf(p4.x, c4.x, local);
        local = fmaf(p4.y, c4.y, local);
        local = fmaf(p4.z, c4.z, local);
        local = fmaf(p4.w, c4.w, local);
    }
    red[threadIdx.x] = local;
    __syncthreads();
    for (int st = 128; st > 0; st >>= 1) {
        if (threadIdx.x < st) red[threadIdx.x] += red[threadIdx.x + st];
        __syncthreads();
    }
    if (threadIdx.x == 0) g_part[row] = red[0];
}

// deterministic per-batch cost reduction
__global__ void kCost(float* __restrict__ cost) {
    __shared__ float red[256];
    int b = blockIdx.x;
    float t = 0.0f;
    #pragma unroll
    for (int k = 0; k < 8; k++)
        t += g_part[b * 2048 + threadIdx.x + k * 256];
    red[threadIdx.x] = t;
    __syncthreads();
    for (int st = 128; st > 0; st >>= 1) {
        if (threadIdx.x < st) red[threadIdx.x] += red[threadIdx.x + st];
        __syncthreads();
    }
    if (threadIdx.x == 0) cost[b] = red[0];
}

extern "C" void kernel_launch(void* const* d_in, const int* in_sizes, int n_in,
                              void* d_out, int out_size) {
    const float* x = (const float*)d_in[0];
    const float* y = (const float*)d_in[1];
    float* out  = (float*)d_out;
    float* cost = out;                        // 4
    float* pi   = out + 4;                    // 16777216
    float* C    = out + 4 + (size_t)NEL;      // 16777216

    float log_mu = logf(1.0f / 2048.0f + 1e-8f);   // == log_nu (P1==P2)
    float eps_log_mu = 0.1f * log_mu;
    float thresh_tot = 0.1f * (float)BB;           // sum-over-all-rows vs thresh*B

    kInit<<<(NROWS + 255) / 256, 256>>>();
    kNorm<<<2 * NROWS / 8, 256>>>(x, y);
    dim3 gC(PP / 64, PP / 64, BB);
    kC<<<gC, 256>>>(x, y, C);
    for (int it = 0; it < 100; it++) {
        kU<<<NROWS / 4, 256>>>(C, it, eps_log_mu);
        kV<<<BB * (PP / 32), 1024>>>(C, it, eps_log_mu, thresh_tot);
    }
    kFinal<<<NROWS, 256>>>(C, pi);
    kCost<<<BB, 256>>>(cost);
}